// round 1
// baseline (speedup 1.0000x reference)
#include <cuda_runtime.h>

// ---------------------------------------------------------------------------
// ftat_BiLSTM: one CTA per batch element, all intermediates in shared memory.
// 512 threads. Stages:
//   A: feature attention (D=7)        B: BiLSTM H=64 (Whh rows in registers)
//   C: temporal attention (S=96)      D: LSTM2 H2=16   E: FC 16->7
// ---------------------------------------------------------------------------

namespace {
constexpr int NT = 512;
constexpr int Sn = 96, Dn = 7;

// shared-memory offsets (in floats)
constexpr int OFF_FA    = 0;        // 96 x 8   (x, later fa)
constexpr int OFF_V     = 768;      // 96 x 8
constexpr int OFF_K     = 1536;     // 96 x 8
constexpr int OFF_Q     = 2304;     // 96 x 8
constexpr int OFF_FATT  = 3072;     // 7 x 8
constexpr int OFF_GATES = 3136;     // 512        (reused as LSTM2 gates)
constexpr int OFF_HBUF  = 3648;     // 128        (reused as LSTM2 h2[16])
constexpr int OFF_LO    = 4096;     // 96 x 64    (0.5*hf ; later lo ; later "to")
constexpr int OFF_LOB   = 10240;    // 96 x 64    (0.5*hb ; later xg2)
constexpr int OFF_TV    = 16384;    // 96 x 68
constexpr int OFF_TK    = 22912;    // 96 x 68
constexpr int OFF_TQ    = 29440;    // 96 x 68
constexpr int OFF_TATT  = 35968;    // 96 x 96
constexpr int OFF_WSTA  = 45184;    // 64 x 68    weight staging tile
constexpr int SMEM_FLOATS = 49536;  // 198144 bytes

constexpr int OFF_WHHST = 16384;    // 256 x 68 staging (overlays TV/TK/TQ, stage-B prologue only)
constexpr int OFF_O2    = 16384;    // 96 x 16 LSTM2 outputs (overlays TV, stage D/E only)
constexpr int OFF_G2    = OFF_GATES;
constexpr int OFF_H2    = OFF_HBUF;

struct Params {
    const float *x;
    const float *fv_w, *fv_b, *fk_w, *fk_b, *fq_w, *fq_b;
    const float *l1f_wih, *l1f_whh, *l1f_bih, *l1f_bhh;
    const float *l1b_wih, *l1b_whh, *l1b_bih, *l1b_bhh;
    const float *tv_w, *tv_b, *tk_w, *tk_b, *tq_w, *tq_b;
    const float *l2_wih, *l2_whh, *l2_bih, *l2_bhh;
    const float *fc_w, *fc_b;
    float *out;
};
} // namespace

__device__ __forceinline__ float sigf(float x) { return 1.0f / (1.0f + __expf(-x)); }
// tanh via exp: accurate to ~1e-7 rel (no approx-tanh MUFU precision risk), saturates cleanly
__device__ __forceinline__ float tanhfast(float x) { return 1.0f - 2.0f / (__expf(2.0f * x) + 1.0f); }

__global__ void __launch_bounds__(512, 1) ftat_bilstm_kernel(Params P) {
    extern __shared__ float sm[];
    const int b = blockIdx.x;
    const int t = threadIdx.x;

    // ================= Stage A: feature attention =================
    {
        const float* x = P.x + (size_t)b * (Sn * Dn);
        for (int idx = t; idx < Sn * Dn; idx += NT) {
            int s = idx / 7, j = idx - s * 7;
            sm[OFF_FA + s * 8 + j] = x[idx];
        }
    }
    __syncthreads();
    // v = x @ fv_w^T + fv_b
    for (int idx = t; idx < Sn * Dn; idx += NT) {
        int s = idx / 7, i = idx - s * 7;
        float a = P.fv_b[i];
#pragma unroll
        for (int j = 0; j < 7; j++) a += sm[OFF_FA + s * 8 + j] * P.fv_w[i * 7 + j];
        sm[OFF_V + s * 8 + i] = a;
    }
    __syncthreads();
    // k = (x+v) @ fk_w^T + fk_b
    for (int idx = t; idx < Sn * Dn; idx += NT) {
        int s = idx / 7, i = idx - s * 7;
        float a = P.fk_b[i];
#pragma unroll
        for (int j = 0; j < 7; j++)
            a += (sm[OFF_FA + s * 8 + j] + sm[OFF_V + s * 8 + j]) * P.fk_w[i * 7 + j];
        sm[OFF_K + s * 8 + i] = a;
    }
    __syncthreads();
    // q = (x+k) @ fq_w^T + fq_b
    for (int idx = t; idx < Sn * Dn; idx += NT) {
        int s = idx / 7, i = idx - s * 7;
        float a = P.fq_b[i];
#pragma unroll
        for (int j = 0; j < 7; j++)
            a += (sm[OFF_FA + s * 8 + j] + sm[OFF_K + s * 8 + j]) * P.fq_w[i * 7 + j];
        sm[OFF_Q + s * 8 + i] = a;
    }
    __syncthreads();
    // fatt logits[i,j] = sum_s q[s,i] * k[s,j]
    if (t < 49) {
        int i = t / 7, j = t - (t / 7) * 7;
        float a = 0.0f;
        for (int s = 0; s < Sn; s++) a += sm[OFF_Q + s * 8 + i] * sm[OFF_K + s * 8 + j];
        sm[OFF_FATT + i * 8 + j] = a;
    }
    __syncthreads();
    // row softmax (7 rows)
    if (t < 7) {
        float* row = sm + OFF_FATT + t * 8;
        float m = row[0];
#pragma unroll
        for (int j = 1; j < 7; j++) m = fmaxf(m, row[j]);
        float ssum = 0.0f;
#pragma unroll
        for (int j = 0; j < 7; j++) { float e = __expf(row[j] - m); row[j] = e; ssum += e; }
        float inv = 1.0f / ssum;
#pragma unroll
        for (int j = 0; j < 7; j++) row[j] *= inv;
    }
    __syncthreads();
    // fa = tanh(v @ fatt + x)   (in-place over x; each element read only by its writer)
    for (int idx = t; idx < Sn * Dn; idx += NT) {
        int s = idx / 7, j = idx - s * 7;
        float a = sm[OFF_FA + s * 8 + j];
#pragma unroll
        for (int i = 0; i < 7; i++) a += sm[OFF_V + s * 8 + i] * sm[OFF_FATT + i * 8 + j];
        sm[OFF_FA + s * 8 + j] = tanhfast(a);
    }
    __syncthreads();

    // ================= Stage B: BiLSTM (H=64) =================
    // thread t: dir = t>>8, gate g = t&255. Whh row held in registers.
    const int dir = t >> 8;
    const int g = t & 255;
    float wreg[64];
    {
        // stage l1f_whh into padded smem (stride 68), pull own row to regs
        for (int idx = t; idx < 256 * 64; idx += NT) {
            int r = idx >> 6, c = idx & 63;
            sm[OFF_WHHST + r * 68 + c] = P.l1f_whh[idx];
        }
        __syncthreads();
        if (dir == 0) {
            const float4* w4 = (const float4*)(sm + OFF_WHHST + g * 68);
#pragma unroll
            for (int j4 = 0; j4 < 16; j4++) {
                float4 wv = w4[j4];
                wreg[4 * j4 + 0] = wv.x; wreg[4 * j4 + 1] = wv.y;
                wreg[4 * j4 + 2] = wv.z; wreg[4 * j4 + 3] = wv.w;
            }
        }
        __syncthreads();
        for (int idx = t; idx < 256 * 64; idx += NT) {
            int r = idx >> 6, c = idx & 63;
            sm[OFF_WHHST + r * 68 + c] = P.l1b_whh[idx];
        }
        __syncthreads();
        if (dir == 1) {
            const float4* w4 = (const float4*)(sm + OFF_WHHST + g * 68);
#pragma unroll
            for (int j4 = 0; j4 < 16; j4++) {
                float4 wv = w4[j4];
                wreg[4 * j4 + 0] = wv.x; wreg[4 * j4 + 1] = wv.y;
                wreg[4 * j4 + 2] = wv.z; wreg[4 * j4 + 3] = wv.w;
            }
        }
        __syncthreads();
    }
    float wi[7];
    float bias;
    {
        const float* wih = dir ? P.l1b_wih : P.l1f_wih;
#pragma unroll
        for (int j = 0; j < 7; j++) wi[j] = wih[g * 7 + j];
        bias = dir ? (P.l1b_bih[g] + P.l1b_bhh[g]) : (P.l1f_bih[g] + P.l1f_bhh[g]);
    }
    if (t < 128) sm[OFF_HBUF + t] = 0.0f;
    float c1 = 0.0f;  // cell state, used by combiner threads t<128
    __syncthreads();

    for (int step = 0; step < Sn; step++) {
        int s = dir ? (Sn - 1 - step) : step;
        float a = bias;
        const float* far = sm + OFF_FA + s * 8;
#pragma unroll
        for (int j = 0; j < 7; j++) a += far[j] * wi[j];
        const float4* h4 = (const float4*)(sm + OFF_HBUF + (dir << 6));
#pragma unroll
        for (int j4 = 0; j4 < 16; j4++) {
            float4 hv = h4[j4];
            a += hv.x * wreg[4 * j4 + 0] + hv.y * wreg[4 * j4 + 1]
               + hv.z * wreg[4 * j4 + 2] + hv.w * wreg[4 * j4 + 3];
        }
        sm[OFF_GATES + t] = a;
        __syncthreads();
        if (t < 128) {
            int d2 = t >> 6, j = t & 63;
            const float* gg = sm + OFF_GATES + (d2 << 8);
            float gi = gg[j], gf = gg[64 + j], gc = gg[128 + j], go = gg[192 + j];
            c1 = sigf(gf) * c1 + sigf(gi) * tanhfast(gc);
            float h = sigf(go) * tanhfast(c1);
            sm[OFF_HBUF + (d2 << 6) + j] = h;
            int ss = d2 ? (Sn - 1 - step) : step;
            sm[(d2 ? OFF_LOB : OFF_LO) + ss * 64 + j] = 0.5f * h;
        }
        __syncthreads();
    }
    // lo = 0.5*hf + 0.5*hb
    for (int idx = t; idx < Sn * 64; idx += NT) sm[OFF_LO + idx] += sm[OFF_LOB + idx];
    __syncthreads();

    // ================= Stage C: temporal attention =================
    // part 1: tv/tk/tq = lo @ W^T + b   (weight rows cached in registers)
    {
        const float* Ws[3] = { P.tv_w, P.tk_w, P.tq_w };
        const float* Bs[3] = { P.tv_b, P.tk_b, P.tq_b };
        const int outs[3] = { OFF_TV, OFF_TK, OFF_TQ };
        for (int m = 0; m < 3; m++) {
            for (int idx = t; idx < 64 * 64; idx += NT) {
                int r = idx >> 6, c = idx & 63;
                sm[OFF_WSTA + r * 68 + c] = Ws[m][idx];
            }
            __syncthreads();
            {
                int i = t & 63, sb = t >> 6;   // 8 blocks x 12 s each
                float w2[64];
                const float4* w4 = (const float4*)(sm + OFF_WSTA + i * 68);
#pragma unroll
                for (int j4 = 0; j4 < 16; j4++) {
                    float4 wv = w4[j4];
                    w2[4 * j4 + 0] = wv.x; w2[4 * j4 + 1] = wv.y;
                    w2[4 * j4 + 2] = wv.z; w2[4 * j4 + 3] = wv.w;
                }
                float bi = Bs[m][i];
                for (int s12 = 0; s12 < 12; s12++) {
                    int s = sb * 12 + s12;
                    float a = bi;
                    const float4* lo4 = (const float4*)(sm + OFF_LO + s * 64);
#pragma unroll
                    for (int j4 = 0; j4 < 16; j4++) {
                        float4 lv = lo4[j4];
                        a += lv.x * w2[4 * j4 + 0] + lv.y * w2[4 * j4 + 1]
                           + lv.z * w2[4 * j4 + 2] + lv.w * w2[4 * j4 + 3];
                    }
                    sm[outs[m] + s * 68 + i] = a;
                }
            }
            __syncthreads();
        }
    }
    // part 2: tatt[i,j] = sum_d tq[i,d]*tk[j,d]
#pragma unroll 1
    for (int r = 0; r < 18; r++) {
        int idx = r * NT + t;          // 0..9215
        int i = idx / 96, j = idx - i * 96;
        float a = 0.0f;
        const float4* q4 = (const float4*)(sm + OFF_TQ + i * 68);
        const float4* k4 = (const float4*)(sm + OFF_TK + j * 68);
#pragma unroll
        for (int d4 = 0; d4 < 16; d4++) {
            float4 qa = q4[d4], ka = k4[d4];
            a += qa.x * ka.x + qa.y * ka.y + qa.z * ka.z + qa.w * ka.w;
        }
        sm[OFF_TATT + idx] = a;
    }
    __syncthreads();
    // row softmax over j (96); one warp per 6 rows
    {
        int w = t >> 5, lane = t & 31;
        for (int rr = 0; rr < 6; rr++) {
            int i = w * 6 + rr;
            float* row = sm + OFF_TATT + i * 96;
            float v0 = row[lane], v1 = row[lane + 32], v2 = row[lane + 64];
            float m = fmaxf(v0, fmaxf(v1, v2));
#pragma unroll
            for (int off = 16; off > 0; off >>= 1) m = fmaxf(m, __shfl_xor_sync(0xffffffffu, m, off));
            float e0 = __expf(v0 - m), e1 = __expf(v1 - m), e2 = __expf(v2 - m);
            float ssum = e0 + e1 + e2;
#pragma unroll
            for (int off = 16; off > 0; off >>= 1) ssum += __shfl_xor_sync(0xffffffffu, ssum, off);
            float inv = 1.0f / ssum;
            row[lane] = e0 * inv; row[lane + 32] = e1 * inv; row[lane + 64] = e2 * inv;
        }
    }
    __syncthreads();
    // part 3: to[i,d] = tanh(sum_j tatt[i,j]*tv[j,d])  -> stored in OFF_LO (stride 64)
    {
        int d = t & 63, ib = t >> 6;
        const float* tvc = sm + OFF_TV + d;
        for (int i12 = 0; i12 < 12; i12++) {
            int i = ib * 12 + i12;
            float a = 0.0f;
            const float4* ta4 = (const float4*)(sm + OFF_TATT + i * 96);
#pragma unroll
            for (int j4 = 0; j4 < 24; j4++) {
                float4 tw = ta4[j4];
                a += tw.x * tvc[(4 * j4 + 0) * 68];
                a += tw.y * tvc[(4 * j4 + 1) * 68];
                a += tw.z * tvc[(4 * j4 + 2) * 68];
                a += tw.w * tvc[(4 * j4 + 3) * 68];
            }
            sm[OFF_LO + i * 64 + d] = tanhfast(a);
        }
    }
    __syncthreads();

    // ================= Stage D: LSTM2 (64 -> 16) =================
    // prologue: xg2[s,g] = to[s] . l2_wih[g] + bih[g] + bhh[g]  -> OFF_LOB
    for (int idx = t; idx < 64 * 64; idx += NT) {
        int r = idx >> 6, c = idx & 63;
        sm[OFF_WSTA + r * 68 + c] = P.l2_wih[idx];
    }
    __syncthreads();
    {
        int g2 = t & 63, sb = t >> 6;
        float w2[64];
        const float4* w4 = (const float4*)(sm + OFF_WSTA + g2 * 68);
#pragma unroll
        for (int j4 = 0; j4 < 16; j4++) {
            float4 wv = w4[j4];
            w2[4 * j4 + 0] = wv.x; w2[4 * j4 + 1] = wv.y;
            w2[4 * j4 + 2] = wv.z; w2[4 * j4 + 3] = wv.w;
        }
        float bi = P.l2_bih[g2] + P.l2_bhh[g2];
        for (int s12 = 0; s12 < 12; s12++) {
            int s = sb * 12 + s12;
            float a = bi;
            const float4* to4 = (const float4*)(sm + OFF_LO + s * 64);
#pragma unroll
            for (int j4 = 0; j4 < 16; j4++) {
                float4 lv = to4[j4];
                a += lv.x * w2[4 * j4 + 0] + lv.y * w2[4 * j4 + 1]
                   + lv.z * w2[4 * j4 + 2] + lv.w * w2[4 * j4 + 3];
            }
            sm[OFF_LOB + s * 64 + g2] = a;
        }
    }
    if (t < 16) sm[OFF_H2 + t] = 0.0f;
    __syncthreads();
    // recurrence: 64 threads (warps 0,1) with named barrier
    if (t < 64) {
        float w22[16];
        {
            const float4* wr = (const float4*)(P.l2_whh + t * 16);
#pragma unroll
            for (int j4 = 0; j4 < 4; j4++) {
                float4 wv = wr[j4];
                w22[4 * j4 + 0] = wv.x; w22[4 * j4 + 1] = wv.y;
                w22[4 * j4 + 2] = wv.z; w22[4 * j4 + 3] = wv.w;
            }
        }
        float c2 = 0.0f;
        for (int s = 0; s < Sn; s++) {
            float a = sm[OFF_LOB + s * 64 + t];
#pragma unroll
            for (int k = 0; k < 16; k++) a += sm[OFF_H2 + k] * w22[k];
            sm[OFF_G2 + t] = a;
            asm volatile("bar.sync 1, 64;" ::: "memory");
            if (t < 16) {
                float gi = sm[OFF_G2 + t], gf = sm[OFF_G2 + 16 + t];
                float gc = sm[OFF_G2 + 32 + t], go = sm[OFF_G2 + 48 + t];
                c2 = sigf(gf) * c2 + sigf(gi) * tanhfast(gc);
                float h = sigf(go) * tanhfast(c2);
                sm[OFF_H2 + t] = h;
                sm[OFF_O2 + s * 16 + t] = h;
            }
            asm volatile("bar.sync 1, 64;" ::: "memory");
        }
    }
    __syncthreads();

    // ================= Stage E: FC 16 -> 7 =================
    {
        float* outp = P.out + (size_t)b * (Sn * Dn);
        for (int idx = t; idx < Sn * Dn; idx += NT) {
            int s = idx / 7, i = idx - s * 7;
            float a = P.fc_b[i];
#pragma unroll
            for (int k = 0; k < 16; k++) a += sm[OFF_O2 + s * 16 + k] * P.fc_w[i * 16 + k];
            outp[idx] = a;
        }
    }
}

extern "C" void kernel_launch(void* const* d_in, const int* in_sizes, int n_in,
                              void* d_out, int out_size) {
    Params P;
    P.x       = (const float*)d_in[0];
    P.fv_w    = (const float*)d_in[1];  P.fv_b = (const float*)d_in[2];
    P.fk_w    = (const float*)d_in[3];  P.fk_b = (const float*)d_in[4];
    P.fq_w    = (const float*)d_in[5];  P.fq_b = (const float*)d_in[6];
    P.l1f_wih = (const float*)d_in[7];  P.l1f_whh = (const float*)d_in[8];
    P.l1f_bih = (const float*)d_in[9];  P.l1f_bhh = (const float*)d_in[10];
    P.l1b_wih = (const float*)d_in[11]; P.l1b_whh = (const float*)d_in[12];
    P.l1b_bih = (const float*)d_in[13]; P.l1b_bhh = (const float*)d_in[14];
    P.tv_w    = (const float*)d_in[15]; P.tv_b = (const float*)d_in[16];
    P.tk_w    = (const float*)d_in[17]; P.tk_b = (const float*)d_in[18];
    P.tq_w    = (const float*)d_in[19]; P.tq_b = (const float*)d_in[20];
    P.l2_wih  = (const float*)d_in[21]; P.l2_whh = (const float*)d_in[22];
    P.l2_bih  = (const float*)d_in[23]; P.l2_bhh = (const float*)d_in[24];
    P.fc_w    = (const float*)d_in[25]; P.fc_b = (const float*)d_in[26];
    P.out     = (float*)d_out;

    const int smem_bytes = SMEM_FLOATS * (int)sizeof(float);
    cudaFuncSetAttribute(ftat_bilstm_kernel,
                         cudaFuncAttributeMaxDynamicSharedMemorySize, smem_bytes);
    ftat_bilstm_kernel<<<2048, NT, smem_bytes>>>(P);
}

// round 2
// speedup vs baseline: 1.0772x; 1.0772x over previous
#include <cuda_runtime.h>

// ---------------------------------------------------------------------------
// ftat_BiLSTM — 4-kernel split:
//  K1 feature attention   (grid 2048 x 128t)  -> g_fa
//  K2 BiLSTM H=64         (grid (2048,2) x 256t, packed f32x2) -> g_lof/g_lob
//  K3 temporal attention  (grid 2048 x 512t, packed f32x2)     -> g_to
//  K4 LSTM2 + FC          (grid 2048 x 256t)  -> out
// ---------------------------------------------------------------------------

namespace {
constexpr int Bn = 2048, Sn = 96, Dn = 7, Hn = 64;
using u64 = unsigned long long;
} // namespace

// scratch (module-load allocated, zero-init .bss)
__device__ float g_fa [Bn * Sn * 8];    // fa, padded stride 8
__device__ float g_lof[Bn * Sn * Hn];   // 0.5*hf
__device__ float g_lob[Bn * Sn * Hn];   // 0.5*hb
__device__ float g_to [Bn * Sn * Hn];   // temporal-attention output

__device__ __forceinline__ float sigf(float x) { return 1.0f / (1.0f + __expf(-x)); }
__device__ __forceinline__ float tanhfast(float x) { return 1.0f - 2.0f / (__expf(2.0f * x) + 1.0f); }

__device__ __forceinline__ u64 ffma2(u64 a, u64 b, u64 c) {
    u64 d; asm("fma.rn.f32x2 %0, %1, %2, %3;" : "=l"(d) : "l"(a), "l"(b), "l"(c)); return d;
}
__device__ __forceinline__ float2 unpack2(u64 v) {
    float2 r; asm("mov.b64 {%0, %1}, %2;" : "=f"(r.x), "=f"(r.y) : "l"(v)); return r;
}
__device__ __forceinline__ u64 dup2(float x) {
    u64 v; asm("mov.b64 %0, {%1, %1};" : "=l"(v) : "f"(x)); return v;
}

// packed dot over 32 u64 (64 floats), 4 chains
__device__ __forceinline__ float dot64_pk(const u64* __restrict__ x, const u64* __restrict__ w) {
    u64 a0 = 0ull, a1 = 0ull, a2 = 0ull, a3 = 0ull;
#pragma unroll
    for (int k = 0; k < 32; k += 4) {
        a0 = ffma2(x[k + 0], w[k + 0], a0);
        a1 = ffma2(x[k + 1], w[k + 1], a1);
        a2 = ffma2(x[k + 2], w[k + 2], a2);
        a3 = ffma2(x[k + 3], w[k + 3], a3);
    }
    float2 f0 = unpack2(a0), f1 = unpack2(a1), f2 = unpack2(a2), f3 = unpack2(a3);
    return ((f0.x + f0.y) + (f1.x + f1.y)) + ((f2.x + f2.y) + (f3.x + f3.y));
}

// =========================== K1: feature attention ===========================
struct P1 {
    const float *x, *fv_w, *fv_b, *fk_w, *fk_b, *fq_w, *fq_b;
};

__global__ void __launch_bounds__(128) k1_featatt(P1 P) {
    __shared__ __align__(16) float sFA[Sn * 8];
    __shared__ __align__(16) float sV[Sn * 8];
    __shared__ __align__(16) float sK[Sn * 8];
    __shared__ __align__(16) float sQ[Sn * 8];
    __shared__ float sATT[7 * 8];
    const int b = blockIdx.x, t = threadIdx.x;
    const float* x = P.x + (size_t)b * (Sn * Dn);
    for (int idx = t; idx < Sn * Dn; idx += 128) {
        int s = idx / 7, j = idx - s * 7;
        sFA[s * 8 + j] = x[idx];
    }
    if (t < Sn) sFA[t * 8 + 7] = 0.0f;
    __syncthreads();
    for (int idx = t; idx < Sn * Dn; idx += 128) {
        int s = idx / 7, i = idx - s * 7;
        float a = P.fv_b[i];
#pragma unroll
        for (int j = 0; j < 7; j++) a += sFA[s * 8 + j] * P.fv_w[i * 7 + j];
        sV[s * 8 + i] = a;
    }
    __syncthreads();
    for (int idx = t; idx < Sn * Dn; idx += 128) {
        int s = idx / 7, i = idx - s * 7;
        float a = P.fk_b[i];
#pragma unroll
        for (int j = 0; j < 7; j++) a += (sFA[s * 8 + j] + sV[s * 8 + j]) * P.fk_w[i * 7 + j];
        sK[s * 8 + i] = a;
    }
    __syncthreads();
    for (int idx = t; idx < Sn * Dn; idx += 128) {
        int s = idx / 7, i = idx - s * 7;
        float a = P.fq_b[i];
#pragma unroll
        for (int j = 0; j < 7; j++) a += (sFA[s * 8 + j] + sK[s * 8 + j]) * P.fq_w[i * 7 + j];
        sQ[s * 8 + i] = a;
    }
    __syncthreads();
    if (t < 49) {
        int i = t / 7, j = t - (t / 7) * 7;
        float a = 0.0f;
        for (int s = 0; s < Sn; s++) a += sQ[s * 8 + i] * sK[s * 8 + j];
        sATT[i * 8 + j] = a;
    }
    __syncthreads();
    if (t < 7) {
        float* row = sATT + t * 8;
        float m = row[0];
#pragma unroll
        for (int j = 1; j < 7; j++) m = fmaxf(m, row[j]);
        float ssum = 0.0f;
#pragma unroll
        for (int j = 0; j < 7; j++) { float e = __expf(row[j] - m); row[j] = e; ssum += e; }
        float inv = 1.0f / ssum;
#pragma unroll
        for (int j = 0; j < 7; j++) row[j] *= inv;
    }
    __syncthreads();
    for (int idx = t; idx < Sn * Dn; idx += 128) {
        int s = idx / 7, j = idx - s * 7;
        float a = sFA[s * 8 + j];
#pragma unroll
        for (int i = 0; i < 7; i++) a += sV[s * 8 + i] * sATT[i * 8 + j];
        sFA[s * 8 + j] = tanhfast(a);
    }
    __syncthreads();
    float* fa = g_fa + (size_t)b * (Sn * 8);
    for (int idx = t; idx < Sn * 8; idx += 128) fa[idx] = sFA[idx];
}

// =========================== K2: BiLSTM ===========================
struct P2 {
    const float *l1f_wih, *l1f_whh, *l1f_bih, *l1f_bhh;
    const float *l1b_wih, *l1b_whh, *l1b_bih, *l1b_bhh;
};

__global__ void __launch_bounds__(256) k2_bilstm(P2 P) {
    __shared__ __align__(16) float sFA[Sn * 8];
    __shared__ __align__(16) float sWST[64 * 68];
    __shared__ __align__(16) float sH[Hn];
    __shared__ float sG[256];
    const int b = blockIdx.x;
    const int dir = blockIdx.y;
    const int t = threadIdx.x;   // gate index g = t

    // load fa
    {
        const float* fa = g_fa + (size_t)b * (Sn * 8);
        for (int idx = t; idx < Sn * 8; idx += 256) sFA[idx] = fa[idx];
    }
    // stage Whh in 4 rounds of 64 rows, grab own row into packed registers
    const float* whh = dir ? P.l1b_whh : P.l1f_whh;
    u64 wpk[32];
#pragma unroll 1
    for (int r = 0; r < 4; r++) {
        for (int idx = t; idx < 64 * 64; idx += 256) {
            int row = idx >> 6, col = idx & 63;
            sWST[row * 68 + col] = whh[(r * 64 + row) * 64 + col];
        }
        __syncthreads();
        if ((t >> 6) == r) {
            const u64* wr = (const u64*)(sWST + (t & 63) * 68);
#pragma unroll
            for (int k = 0; k < 32; k++) wpk[k] = wr[k];
        }
        __syncthreads();
    }
    float wi[7], bias;
    {
        const float* wih = dir ? P.l1b_wih : P.l1f_wih;
#pragma unroll
        for (int j = 0; j < 7; j++) wi[j] = wih[t * 7 + j];
        bias = dir ? (P.l1b_bih[t] + P.l1b_bhh[t]) : (P.l1f_bih[t] + P.l1f_bhh[t]);
    }
    if (t < Hn) sH[t] = 0.0f;
    float c1 = 0.0f;
    __syncthreads();

    float* lo = (dir ? g_lob : g_lof) + (size_t)b * (Sn * Hn);
    const u64* h2 = (const u64*)sH;

#pragma unroll 1
    for (int step = 0; step < Sn; step++) {
        int s = dir ? (Sn - 1 - step) : step;
        float a = bias;
        const float* far = sFA + s * 8;
#pragma unroll
        for (int j = 0; j < 7; j++) a += far[j] * wi[j];
        a += dot64_pk(h2, wpk);
        sG[t] = a;
        __syncthreads();
        if (t < Hn) {
            float gi = sG[t], gf = sG[64 + t], gc = sG[128 + t], go = sG[192 + t];
            c1 = sigf(gf) * c1 + sigf(gi) * tanhfast(gc);
            float h = sigf(go) * tanhfast(c1);
            sH[t] = h;
            lo[s * Hn + t] = 0.5f * h;
        }
        __syncthreads();
    }
}

// =========================== K3: temporal attention ===========================
struct P3 {
    const float *tv_w, *tv_b, *tk_w, *tk_b, *tq_w, *tq_b;
};

namespace {
constexpr int K3_LO   = 0;       // 96 x 64
constexpr int K3_TV   = 6144;    // 96 x 68
constexpr int K3_TK   = 12672;   // 96 x 68
constexpr int K3_TQ   = 19200;   // 96 x 68
constexpr int K3_TATT = 25728;   // 96 x 96
constexpr int K3_WST  = 34944;   // 64 x 68
constexpr int K3_FLOATS = 39296; // 157184 bytes
}

__global__ void __launch_bounds__(512, 1) k3_tempatt(P3 P) {
    extern __shared__ float sm[];
    const int b = blockIdx.x, t = threadIdx.x;

    // lo = 0.5 hf + 0.5 hb
    {
        const float* lf = g_lof + (size_t)b * (Sn * Hn);
        const float* lb = g_lob + (size_t)b * (Sn * Hn);
        for (int idx = t; idx < Sn * Hn; idx += 512) sm[K3_LO + idx] = lf[idx] + lb[idx];
    }
    __syncthreads();

    // part 1: tv/tk/tq = lo @ W^T + b
    {
        const float* Ws[3] = { P.tv_w, P.tk_w, P.tq_w };
        const float* Bs[3] = { P.tv_b, P.tk_b, P.tq_b };
        const int outs[3] = { K3_TV, K3_TK, K3_TQ };
#pragma unroll 1
        for (int m = 0; m < 3; m++) {
            for (int idx = t; idx < 64 * 64; idx += 512) {
                int row = idx >> 6, col = idx & 63;
                sm[K3_WST + row * 68 + col] = Ws[m][idx];
            }
            __syncthreads();
            {
                int i = t & 63, sb = t >> 6;
                u64 wpk[32];
                const u64* wr = (const u64*)(sm + K3_WST + i * 68);
#pragma unroll
                for (int k = 0; k < 32; k++) wpk[k] = wr[k];
                float bi = Bs[m][i];
                for (int s12 = 0; s12 < 12; s12++) {
                    int s = sb * 12 + s12;
                    const u64* lor = (const u64*)(sm + K3_LO + s * 64);
                    sm[outs[m] + s * 68 + i] = bi + dot64_pk(lor, wpk);
                }
            }
            __syncthreads();
        }
    }

    // part 2: tatt[i,j] = tq[i,:].tk[j,:]
#pragma unroll 1
    for (int r = 0; r < 18; r++) {
        int idx = r * 512 + t;
        int i = idx / 96, j = idx - i * 96;
        const u64* q2 = (const u64*)(sm + K3_TQ + i * 68);
        const u64* k2 = (const u64*)(sm + K3_TK + j * 68);
        sm[K3_TATT + idx] = dot64_pk(q2, k2);
    }
    __syncthreads();

    // softmax rows (one warp per 6 rows)
    {
        int w = t >> 5, lane = t & 31;
        for (int rr = 0; rr < 6; rr++) {
            int i = w * 6 + rr;
            float* row = sm + K3_TATT + i * 96;
            float v0 = row[lane], v1 = row[lane + 32], v2 = row[lane + 64];
            float m = fmaxf(v0, fmaxf(v1, v2));
#pragma unroll
            for (int off = 16; off > 0; off >>= 1) m = fmaxf(m, __shfl_xor_sync(0xffffffffu, m, off));
            float e0 = __expf(v0 - m), e1 = __expf(v1 - m), e2 = __expf(v2 - m);
            float ssum = e0 + e1 + e2;
#pragma unroll
            for (int off = 16; off > 0; off >>= 1) ssum += __shfl_xor_sync(0xffffffffu, ssum, off);
            float inv = 1.0f / ssum;
            row[lane] = e0 * inv; row[lane + 32] = e1 * inv; row[lane + 64] = e2 * inv;
        }
    }
    __syncthreads();

    // part 3: to[i,:] = tanh(tatt[i,:] @ tv)  (packed over feature dim)
    {
        int dp = t & 31, ib = t >> 5;   // d = 2*dp ; 16 groups x 6 rows
        float* top = g_to + (size_t)b * (Sn * Hn);
        for (int i6 = 0; i6 < 6; i6++) {
            int i = ib * 6 + i6;
            const float* tar = sm + K3_TATT + i * 96;
            u64 a0 = 0ull, a1 = 0ull;
#pragma unroll
            for (int j = 0; j < 96; j += 2) {
                u64 tv0 = *(const u64*)(sm + K3_TV + j * 68 + 2 * dp);
                u64 tv1 = *(const u64*)(sm + K3_TV + (j + 1) * 68 + 2 * dp);
                a0 = ffma2(dup2(tar[j]), tv0, a0);
                a1 = ffma2(dup2(tar[j + 1]), tv1, a1);
            }
            float2 f0 = unpack2(a0), f1 = unpack2(a1);
            float2 o = make_float2(tanhfast(f0.x + f1.x), tanhfast(f0.y + f1.y));
            *(float2*)(top + i * 64 + 2 * dp) = o;
        }
    }
}

// =========================== K4: LSTM2 + FC ===========================
struct P4 {
    const float *l2_wih, *l2_whh, *l2_bih, *l2_bhh, *fc_w, *fc_b;
    float* out;
};

namespace {
constexpr int K4_TO  = 0;        // 96 x 64
constexpr int K4_XG  = 6144;     // 96 x 64
constexpr int K4_WST = 12288;    // 64 x 68
constexpr int K4_O2  = 16640;    // 96 x 16
constexpr int K4_G2  = 18176;    // 64
constexpr int K4_H2  = 18240;    // 16
constexpr int K4_FLOATS = 18272; // 73088 bytes
}

__global__ void __launch_bounds__(256) k4_lstm2fc(P4 P) {
    extern __shared__ float sm[];
    const int b = blockIdx.x, t = threadIdx.x;

    {
        const float* top = g_to + (size_t)b * (Sn * Hn);
        for (int idx = t; idx < Sn * Hn; idx += 256) sm[K4_TO + idx] = top[idx];
    }
    for (int idx = t; idx < 64 * 64; idx += 256) {
        int row = idx >> 6, col = idx & 63;
        sm[K4_WST + row * 68 + col] = P.l2_wih[idx];
    }
    __syncthreads();
    // prologue: xg2[s,g] = to[s] . wih[g] + bih + bhh
    {
        int g2 = t & 63, sb = t >> 6;
        u64 wpk[32];
        const u64* wr = (const u64*)(sm + K4_WST + g2 * 68);
#pragma unroll
        for (int k = 0; k < 32; k++) wpk[k] = wr[k];
        float bi = P.l2_bih[g2] + P.l2_bhh[g2];
        for (int s24 = 0; s24 < 24; s24++) {
            int s = sb * 24 + s24;
            const u64* tor = (const u64*)(sm + K4_TO + s * 64);
            sm[K4_XG + s * 64 + g2] = bi + dot64_pk(tor, wpk);
        }
    }
    if (t < 16) sm[K4_H2 + t] = 0.0f;
    __syncthreads();

    if (t < 64) {
        u64 w22[8];
        {
            const u64* wr = (const u64*)(P.l2_whh + t * 16);
#pragma unroll
            for (int k = 0; k < 8; k++) w22[k] = wr[k];
        }
        const u64* h2 = (const u64*)(sm + K4_H2);
        float c2 = 0.0f;
#pragma unroll 1
        for (int s = 0; s < Sn; s++) {
            u64 a0 = 0ull, a1 = 0ull;
#pragma unroll
            for (int k = 0; k < 8; k += 2) {
                a0 = ffma2(h2[k], w22[k], a0);
                a1 = ffma2(h2[k + 1], w22[k + 1], a1);
            }
            float2 f0 = unpack2(a0), f1 = unpack2(a1);
            float a = sm[K4_XG + s * 64 + t] + (f0.x + f0.y) + (f1.x + f1.y);
            sm[K4_G2 + t] = a;
            asm volatile("bar.sync 1, 64;" ::: "memory");
            if (t < 16) {
                float gi = sm[K4_G2 + t], gf = sm[K4_G2 + 16 + t];
                float gc = sm[K4_G2 + 32 + t], go = sm[K4_G2 + 48 + t];
                c2 = sigf(gf) * c2 + sigf(gi) * tanhfast(gc);
                float h = sigf(go) * tanhfast(c2);
                sm[K4_H2 + t] = h;
                sm[K4_O2 + s * 16 + t] = h;
            }
            asm volatile("bar.sync 1, 64;" ::: "memory");
        }
    }
    __syncthreads();

    {
        float* outp = P.out + (size_t)b * (Sn * Dn);
        for (int idx = t; idx < Sn * Dn; idx += 256) {
            int s = idx / 7, i = idx - s * 7;
            float a = P.fc_b[i];
#pragma unroll
            for (int k = 0; k < 16; k++) a += sm[K4_O2 + s * 16 + k] * P.fc_w[i * 16 + k];
            outp[idx] = a;
        }
    }
}

// =========================== launch ===========================
extern "C" void kernel_launch(void* const* d_in, const int* in_sizes, int n_in,
                              void* d_out, int out_size) {
    P1 p1; P2 p2; P3 p3; P4 p4;
    p1.x       = (const float*)d_in[0];
    p1.fv_w    = (const float*)d_in[1];  p1.fv_b = (const float*)d_in[2];
    p1.fk_w    = (const float*)d_in[3];  p1.fk_b = (const float*)d_in[4];
    p1.fq_w    = (const float*)d_in[5];  p1.fq_b = (const float*)d_in[6];
    p2.l1f_wih = (const float*)d_in[7];  p2.l1f_whh = (const float*)d_in[8];
    p2.l1f_bih = (const float*)d_in[9];  p2.l1f_bhh = (const float*)d_in[10];
    p2.l1b_wih = (const float*)d_in[11]; p2.l1b_whh = (const float*)d_in[12];
    p2.l1b_bih = (const float*)d_in[13]; p2.l1b_bhh = (const float*)d_in[14];
    p3.tv_w    = (const float*)d_in[15]; p3.tv_b = (const float*)d_in[16];
    p3.tk_w    = (const float*)d_in[17]; p3.tk_b = (const float*)d_in[18];
    p3.tq_w    = (const float*)d_in[19]; p3.tq_b = (const float*)d_in[20];
    p4.l2_wih  = (const float*)d_in[21]; p4.l2_whh = (const float*)d_in[22];
    p4.l2_bih  = (const float*)d_in[23]; p4.l2_bhh = (const float*)d_in[24];
    p4.fc_w    = (const float*)d_in[25]; p4.fc_b = (const float*)d_in[26];
    p4.out     = (float*)d_out;

    cudaFuncSetAttribute(k3_tempatt, cudaFuncAttributeMaxDynamicSharedMemorySize,
                         K3_FLOATS * (int)sizeof(float));
    cudaFuncSetAttribute(k4_lstm2fc, cudaFuncAttributeMaxDynamicSharedMemorySize,
                         K4_FLOATS * (int)sizeof(float));

    k1_featatt<<<Bn, 128>>>(p1);
    k2_bilstm<<<dim3(Bn, 2), 256>>>(p2);
    k3_tempatt<<<Bn, 512, K3_FLOATS * sizeof(float)>>>(p3);
    k4_lstm2fc<<<Bn, 256, K4_FLOATS * sizeof(float)>>>(p4);
}